// round 9
// baseline (speedup 1.0000x reference)
#include <cuda_runtime.h>
#include <cuda_bf16.h>
#include <math_constants.h>
#include <cstdint>

#define N_ROWS  16384       // b*h*w
#define D_DIM   256
#define K_CODES 8192
#define HW      1024
#define ZQ_ELEMS (16 * 256 * 1024)
#define NT      64          // code tiles of 128
#define C1_T    1.25e-6f    // per-row error slope (covers bf16 rounding of z,e)
#define C0_T    1.6e-4f     // fixed slack: fp32 reorder + expr rounding + grid ulps + enorm

// ---------------- scratch ----------------------------------------------------
__device__ __align__(16) float          g_zt[N_ROWS * D_DIM];
__device__ __align__(16) __nv_bfloat16  g_zbf[N_ROWS * D_DIM];
__device__ __align__(16) __nv_bfloat16  g_cbbf[K_CODES * D_DIM];
__device__ float g_znorm[N_ROWS];
__device__ float g_zn1[N_ROWS];
__device__ float g_enorm[K_CODES];
__device__ float g_tmin[N_ROWS * 256];       // per (row, tile, code-quadrant) min
__device__ __align__(16) uint32_t g_mask[N_ROWS * NT * 4];
__device__ int   g_idx[N_ROWS];
__device__ float g_partial[4096];

__device__ __forceinline__ uint32_t smem_u32(const void* p) {
    uint32_t a;
    asm("{ .reg .u64 t; cvta.to.shared.u64 t, %1; cvt.u32.u64 %0, t; }" : "=r"(a) : "l"(p));
    return a;
}
#define LDM4(r, a) \
    asm volatile("ldmatrix.sync.aligned.m8n8.x4.shared.b16 {%0,%1,%2,%3}, [%4];" \
        : "=r"((r)[0]), "=r"((r)[1]), "=r"((r)[2]), "=r"((r)[3]) : "r"(a))
#define MMA16816(d, a, b0, b1) \
    asm volatile("mma.sync.aligned.m16n8k16.row.col.f32.bf16.bf16.f32 " \
        "{%0,%1,%2,%3}, {%4,%5,%6,%7}, {%8,%9}, {%0,%1,%2,%3};" \
        : "+f"((d)[0]), "+f"((d)[1]), "+f"((d)[2]), "+f"((d)[3]) \
        : "r"((a)[0]), "r"((a)[1]), "r"((a)[2]), "r"((a)[3]), "r"(b0), "r"(b1))
#define CP_ASYNC16(s, g) \
    asm volatile("cp.async.cg.shared.global [%0], [%1], 16;" :: "r"(s), "l"(g) : "memory")
#define CP_COMMIT()  asm volatile("cp.async.commit_group;" ::: "memory")
#define CP_WAIT0()   asm volatile("cp.async.wait_group 0;" ::: "memory")

// threshold: identical expression in screen and rescore
__device__ __forceinline__ float t_row(float zn1) {
    return fmaf(zn1, C1_T, C0_T);
}

// ---------------- kernel 1: transpose + bf16 copy ---------------------------
__global__ void k_transpose(const float* __restrict__ z) {
    __shared__ float t[32][33];
    const int b = blockIdx.z, c0 = blockIdx.x * 32, hw0 = blockIdx.y * 32;
    const int tx = threadIdx.x & 31, ty = threadIdx.x >> 5;
    const float* zp = z + ((size_t)b * 256 + c0) * HW + hw0;
#pragma unroll
    for (int i = 0; i < 4; i++)
        t[ty + i * 8][tx] = zp[(size_t)(ty + i * 8) * HW + tx];
    __syncthreads();
    const size_t base = ((size_t)(b * HW + hw0)) * D_DIM + c0;
#pragma unroll
    for (int i = 0; i < 4; i++) {
        float v = t[tx][ty + i * 8];
        g_zt[base + (size_t)(ty + i * 8) * D_DIM + tx]  = v;
        g_zbf[base + (size_t)(ty + i * 8) * D_DIM + tx] = __float2bfloat16_rn(v);
    }
}

// ---------------- kernel 2: codebook -> bf16 + enorm (fused) -----------------
__global__ void k_cbprep(const float* __restrict__ cb) {
    const int warp = (blockIdx.x * 256 + threadIdx.x) >> 5;
    const int lane = threadIdx.x & 31;
    const float* src = cb + (size_t)warp * D_DIM;
    float s = 0.f;
#pragma unroll
    for (int i = 0; i < 8; i++) {
        float v = src[lane + i * 32];
        s = fmaf(v, v, s);
    }
#pragma unroll
    for (int o = 16; o; o >>= 1) s += __shfl_xor_sync(0xffffffffu, s, o);
    if (lane == 0) g_enorm[warp] = s;

    float4 v0 = *(const float4*)(src + lane * 8);
    float4 v1 = *(const float4*)(src + lane * 8 + 4);
    __nv_bfloat162 p0{__float2bfloat16_rn(v0.x), __float2bfloat16_rn(v0.y)};
    __nv_bfloat162 p1{__float2bfloat16_rn(v0.z), __float2bfloat16_rn(v0.w)};
    __nv_bfloat162 p2{__float2bfloat16_rn(v1.x), __float2bfloat16_rn(v1.y)};
    __nv_bfloat162 p3{__float2bfloat16_rn(v1.z), __float2bfloat16_rn(v1.w)};
    uint4 o;
    o.x = *(uint32_t*)&p0; o.y = *(uint32_t*)&p1;
    o.z = *(uint32_t*)&p2; o.w = *(uint32_t*)&p3;
    *(uint4*)(g_cbbf + (size_t)warp * D_DIM + lane * 8) = o;
}

// ---------------- kernel 3: z norms ------------------------------------------
__global__ void k_norms() {
    const int warp = (blockIdx.x * 256 + threadIdx.x) >> 5;
    const int lane = threadIdx.x & 31;
    const float* src = g_zt + (size_t)warp * D_DIM;
    float s = 0.f, s1 = 0.f;
#pragma unroll
    for (int i = 0; i < 8; i++) {
        float v = src[lane + i * 32];
        s  = fmaf(v, v, s);
        s1 += fabsf(v);
    }
#pragma unroll
    for (int o = 16; o; o >>= 1) {
        s  += __shfl_xor_sync(0xffffffffu, s, o);
        s1 += __shfl_xor_sync(0xffffffffu, s1, o);
    }
    if (lane == 0) { g_znorm[warp] = s; g_zn1[warp] = s1; }
}

// ---- kernel 4: HMMA screen, 64x32 warp tiles + fragment double-buffer -------
#define SM_A    0
#define SM_B0   65536
#define SM_B1   131072
#define SMEM_TOTAL 196608

__device__ __forceinline__ void stage_async(const __nv_bfloat16* __restrict__ g,
                                            uint32_t sdst, int tid) {
#pragma unroll
    for (int it = 0; it < 16; it++) {
        const int idx = it * 256 + tid;
        const int row = idx >> 5, ch = idx & 31;
        CP_ASYNC16(sdst + row * 512 + ((ch ^ (row & 7)) << 4),
                   g + (size_t)row * 256 + ch * 8);
    }
}

__global__ __launch_bounds__(256, 1) void k_screen() {
    extern __shared__ char smem[];
    const int tid = threadIdx.x, w = tid >> 5, lane = tid & 31;
    const int wm = (w >> 2) * 64, wc = w & 3, wn = wc * 32;
    const int gid = lane >> 2, tg = lane & 3, ls = lane & 7;
    const int row0 = blockIdx.x * 128;
    const uint32_t sb = smem_u32(smem);

    stage_async(g_zbf + (size_t)row0 * D_DIM, sb + SM_A, tid);
    stage_async(g_cbbf, sb + SM_B0, tid);
    CP_COMMIT();

    int rows[8]; float znr[8], Trw[8];
#pragma unroll
    for (int k = 0; k < 8; k++) {
        const int r = wm + (k >> 1) * 16 + (k & 1) * 8 + gid;
        rows[k] = r;
        znr[k]  = g_znorm[row0 + r];
        Trw[k]  = t_row(g_zn1[row0 + r]);
    }

    const int kmA = lane >> 4;
    const int kmB = (lane >> 3) & 1;
    uint32_t baA[4];
#pragma unroll
    for (int i = 0; i < 4; i++) {
        const int r = wm + i * 16 + ((lane >> 3) & 1) * 8 + ls;
        baA[i] = sb + SM_A + r * 512;
    }
    uint32_t boff[2];
#pragma unroll
    for (int p = 0; p < 2; p++) {
        const int r = wn + (p * 2 + (lane >> 4)) * 8 + ls;
        boff[p] = r * 512;
    }

    float acc[4][4][4];
#pragma unroll
    for (int i = 0; i < 4; i++)
#pragma unroll
        for (int j = 0; j < 4; j++)
#pragma unroll
            for (int c = 0; c < 4; c++) acc[i][j][c] = 0.f;

    CP_WAIT0();
    __syncthreads();

    for (int t = 0; t < NT; t++) {
        const uint32_t bbase = sb + ((t & 1) ? SM_B1 : SM_B0);
        if (t + 1 < NT) {
            stage_async(g_cbbf + (size_t)(t + 1) * 128 * D_DIM,
                        sb + (((t + 1) & 1) ? SM_B1 : SM_B0), tid);
            CP_COMMIT();
        }

        // fragment double-buffer: load kc=0, then prefetch kc+1 before MMA(kc)
        uint32_t a[2][4][4], bq[2][2][4];
        {
            const uint32_t offA = (uint32_t)((kmA ^ ls) << 4);
            const uint32_t offB = (uint32_t)((kmB ^ ls) << 4);
#pragma unroll
            for (int i = 0; i < 4; i++) LDM4(a[0][i], baA[i] + offA);
            LDM4(bq[0][0], bbase + boff[0] + offB);
            LDM4(bq[0][1], bbase + boff[1] + offB);
        }
#pragma unroll
        for (int kc = 0; kc < 16; kc++) {
            const int cur = kc & 1, nxt = cur ^ 1;
            if (kc < 15) {
                const uint32_t offA = (uint32_t)(((2 * (kc + 1) + kmA) ^ ls) << 4);
                const uint32_t offB = (uint32_t)(((2 * (kc + 1) + kmB) ^ ls) << 4);
#pragma unroll
                for (int i = 0; i < 4; i++) LDM4(a[nxt][i], baA[i] + offA);
                LDM4(bq[nxt][0], bbase + boff[0] + offB);
                LDM4(bq[nxt][1], bbase + boff[1] + offB);
            }
#pragma unroll
            for (int i = 0; i < 4; i++)
#pragma unroll
                for (int j = 0; j < 4; j++)
                    MMA16816(acc[i][j], a[cur][i], bq[cur][j >> 1][(j & 1) * 2],
                             bq[cur][j >> 1][(j & 1) * 2 + 1]);
        }

        // ---- all-register epilogue: per-warp min + superset mask (no enorm) ----
        float rmin[8];
#pragma unroll
        for (int k = 0; k < 8; k++) rmin[k] = CUDART_INF_F;
#pragma unroll
        for (int i = 0; i < 4; i++)
#pragma unroll
            for (int j = 0; j < 4; j++)
#pragma unroll
                for (int c = 0; c < 4; c++) {
                    const int k = i * 2 + (c >> 1);
                    const float s = fmaf(-2.f, acc[i][j][c], znr[k]);
                    rmin[k] = fminf(rmin[k], s);
                }
#pragma unroll
        for (int k = 0; k < 8; k++) {
            rmin[k] = fminf(rmin[k], __shfl_xor_sync(0xffffffffu, rmin[k], 1));
            rmin[k] = fminf(rmin[k], __shfl_xor_sync(0xffffffffu, rmin[k], 2));
        }
        uint32_t m[8] = {0, 0, 0, 0, 0, 0, 0, 0};
#pragma unroll
        for (int i = 0; i < 4; i++)
#pragma unroll
            for (int j = 0; j < 4; j++)
#pragma unroll
                for (int c = 0; c < 4; c++) {
                    const int k = i * 2 + (c >> 1);
                    const float s = fmaf(-2.f, acc[i][j][c], znr[k]);
                    if (s < rmin[k] + Trw[k]) m[k] |= 1u << (j * 8 + tg * 2 + (c & 1));
                }
#pragma unroll
        for (int k = 0; k < 8; k++) {
            m[k] |= __shfl_xor_sync(0xffffffffu, m[k], 1);
            m[k] |= __shfl_xor_sync(0xffffffffu, m[k], 2);
        }
        if (tg == 0) {
#pragma unroll
            for (int k = 0; k < 8; k++) {
                g_mask[((size_t)(row0 + rows[k]) * NT + t) * 4 + wc] = m[k];
                g_tmin[(size_t)(row0 + rows[k]) * 256 + t * 4 + wc]  = rmin[k];
            }
        }
#pragma unroll
        for (int i = 0; i < 4; i++)
#pragma unroll
            for (int j = 0; j < 4; j++)
#pragma unroll
                for (int c = 0; c < 4; c++) acc[i][j][c] = 0.f;
        CP_WAIT0();
        __syncthreads();
    }
}

// ---------------- kernel 5: exact fp32 rescore (pipelined candidate dot) -----
__global__ void k_rescore(const float* __restrict__ cb, float* __restrict__ oidx) {
    __shared__ float zrow[256];
    __shared__ float smin2[64];
    __shared__ float sd[64];
    __shared__ int   si[64];
    const int row = blockIdx.x, tid = threadIdx.x;
    const float4 tm4 = ((const float4*)g_tmin)[row * 64 + tid];
    const float tml = fminf(fminf(tm4.x, tm4.y), fminf(tm4.z, tm4.w));
    smin2[tid] = tml;
#pragma unroll
    for (int i = tid; i < 256; i += 64) zrow[i] = g_zt[(size_t)row * D_DIM + i];
    __syncthreads();
    for (int o = 32; o; o >>= 1) {
        if (tid < o) smin2[tid] = fminf(smin2[tid], smin2[tid + o]);
        __syncthreads();
    }
    const float m    = smin2[0];
    const float Trow = t_row(g_zn1[row]);
    const float zn   = g_znorm[row];
    const float tmv[4] = {tm4.x, tm4.y, tm4.z, tm4.w};

    float bd = CUDART_INF_F; int bi = 0x7fffffff;
#pragma unroll
    for (int q = 0; q < 4; q++) {
        if (tmv[q] < m + Trow) {
            uint32_t bits = g_mask[((size_t)row * NT + tid) * 4 + q];
            while (bits) {
                const int j = __ffs(bits) - 1; bits &= bits - 1;
                const int k = tid * 128 + q * 32 + j;
                const float4* e4 = (const float4*)(cb + (size_t)k * D_DIM);
                // double-buffered float4 chunk loads; fmaf order d0=0..255 UNCHANGED
                float4 buf0[8], buf1[8];
#pragma unroll
                for (int i = 0; i < 8; i++) buf0[i] = __ldg(e4 + i);
                float acc = 0.f;
#pragma unroll
                for (int ch = 0; ch < 8; ch++) {
                    const float4* cur = (ch & 1) ? buf1 : buf0;
                    float4*       nxt = (ch & 1) ? buf0 : buf1;
                    if (ch < 7) {
#pragma unroll
                        for (int i = 0; i < 8; i++) nxt[i] = __ldg(e4 + (ch + 1) * 8 + i);
                    }
#pragma unroll
                    for (int i = 0; i < 8; i++) {
                        const int d0 = ch * 32 + i * 4;
                        acc = fmaf(zrow[d0],     cur[i].x, acc);
                        acc = fmaf(zrow[d0 + 1], cur[i].y, acc);
                        acc = fmaf(zrow[d0 + 2], cur[i].z, acc);
                        acc = fmaf(zrow[d0 + 3], cur[i].w, acc);
                    }
                }
                const float s   = zn + __ldg(&g_enorm[k]);
                const float dsc = s - 2.0f * acc;
                if (dsc < bd || (dsc == bd && k < bi)) { bd = dsc; bi = k; }
            }
        }
    }
    sd[tid] = bd; si[tid] = bi;
    __syncthreads();
    for (int o = 32; o; o >>= 1) {
        if (tid < o) {
            const float d2 = sd[tid + o]; const int i2 = si[tid + o];
            if (d2 < sd[tid] || (d2 == sd[tid] && i2 < si[tid])) { sd[tid] = d2; si[tid] = i2; }
        }
        __syncthreads();
    }
    if (tid == 0) { g_idx[row] = si[0]; oidx[row] = (float)si[0]; }
}

// ---------------- kernel 6: gather + straight-through + loss partials --------
__global__ void k_gather(const float* __restrict__ z, const float* __restrict__ cb,
                         float* __restrict__ out) {
    const int c = blockIdx.x, b = blockIdx.y;
    const float* zp = z   + ((size_t)b * D_DIM + c) * HW;
    float*       op = out + ((size_t)b * D_DIM + c) * HW;
    float part = 0.f;
#pragma unroll
    for (int it = 0; it < 4; it++) {
        const int hw  = it * 256 + threadIdx.x;
        const int idx = g_idx[b * HW + hw];
        float q  = __ldg(cb + (size_t)idx * D_DIM + c);
        float zv = zp[hw];
        float t  = q - zv;
        op[hw]   = zv + t;
        part     = fmaf(t, t, part);
    }
    __shared__ float sm[8];
    const int lane = threadIdx.x & 31, ww = threadIdx.x >> 5;
#pragma unroll
    for (int o = 16; o; o >>= 1) part += __shfl_xor_sync(0xffffffffu, part, o);
    if (lane == 0) sm[ww] = part;
    __syncthreads();
    if (threadIdx.x == 0) {
        float s = 0.f;
        for (int i = 0; i < 8; i++) s += sm[i];
        g_partial[b * 256 + c] = s;
    }
}

// ---------------- kernel 7: loss finalize ------------------------------------
__global__ void k_loss(float* __restrict__ out) {
    __shared__ float sm[256];
    const int tid = threadIdx.x;
    float s = 0.f;
#pragma unroll
    for (int i = 0; i < 16; i++) s += g_partial[tid * 16 + i];
    sm[tid] = s;
    __syncthreads();
    for (int o = 128; o; o >>= 1) {
        if (tid < o) sm[tid] += sm[tid + o];
        __syncthreads();
    }
    if (tid == 0) {
        const float m = sm[0] / (float)ZQ_ELEMS;
        out[ZQ_ELEMS] = m + 0.25f * m;
    }
}

// ---------------- launcher ---------------------------------------------------
extern "C" void kernel_launch(void* const* d_in, const int* in_sizes, int n_in,
                              void* d_out, int out_size) {
    const float* z  = (const float*)d_in[0];
    const float* cb = (const float*)d_in[1];
    float* out = (float*)d_out;

    static int attr_set = 0;
    if (!attr_set) {
        cudaFuncSetAttribute(k_screen, cudaFuncAttributeMaxDynamicSharedMemorySize,
                             SMEM_TOTAL);
        attr_set = 1;
    }

    dim3 gT(8, 32, 16);
    k_transpose<<<gT, 256>>>(z);
    k_cbprep<<<1024, 256>>>(cb);
    k_norms<<<2048, 256>>>();
    k_screen<<<128, 256, SMEM_TOTAL>>>();
    k_rescore<<<N_ROWS, 64>>>(cb, out + ZQ_ELEMS + 1);
    dim3 gG(256, 16);
    k_gather<<<gG, 256>>>(z, cb, out);
    k_loss<<<1, 256>>>(out);
}

// round 10
// speedup vs baseline: 1.0247x; 1.0247x over previous
#include <cuda_runtime.h>
#include <cuda_bf16.h>
#include <math_constants.h>
#include <cstdint>

#define N_ROWS  16384       // b*h*w
#define D_DIM   256
#define K_CODES 8192
#define HW      1024
#define ZQ_ELEMS (16 * 256 * 1024)
#define NT      64          // code tiles of 128
#define C1_T    1.25e-6f    // per-row error slope (covers bf16 rounding of z,e)
#define C0_T    1.6e-4f     // fixed slack: fp32 reorder + expr rounding + grid ulps + enorm

// ---------------- scratch ----------------------------------------------------
__device__ __align__(16) __nv_bfloat16  g_cbbf[K_CODES * D_DIM];
__device__ float g_znorm[N_ROWS];
__device__ float g_zn1[N_ROWS];
__device__ float g_enorm[K_CODES];
__device__ float g_tmin[N_ROWS * 256];       // per (row, tile, code-quadrant) min
__device__ __align__(16) uint32_t g_mask[N_ROWS * NT * 4];
__device__ int   g_idx[N_ROWS];
__device__ float g_partial[4096];

__device__ __forceinline__ uint32_t smem_u32(const void* p) {
    uint32_t a;
    asm("{ .reg .u64 t; cvta.to.shared.u64 t, %1; cvt.u32.u64 %0, t; }" : "=r"(a) : "l"(p));
    return a;
}
#define LDM4(r, a) \
    asm volatile("ldmatrix.sync.aligned.m8n8.x4.shared.b16 {%0,%1,%2,%3}, [%4];" \
        : "=r"((r)[0]), "=r"((r)[1]), "=r"((r)[2]), "=r"((r)[3]) : "r"(a))
#define MMA16816(d, a, b0, b1) \
    asm volatile("mma.sync.aligned.m16n8k16.row.col.f32.bf16.bf16.f32 " \
        "{%0,%1,%2,%3}, {%4,%5,%6,%7}, {%8,%9}, {%0,%1,%2,%3};" \
        : "+f"((d)[0]), "+f"((d)[1]), "+f"((d)[2]), "+f"((d)[3]) \
        : "r"((a)[0]), "r"((a)[1]), "r"((a)[2]), "r"((a)[3]), "r"(b0), "r"(b1))
#define CP_ASYNC16(s, g) \
    asm volatile("cp.async.cg.shared.global [%0], [%1], 16;" :: "r"(s), "l"(g) : "memory")
#define CP_COMMIT()  asm volatile("cp.async.commit_group;" ::: "memory")
#define CP_WAIT0()   asm volatile("cp.async.wait_group 0;" ::: "memory")

// threshold: identical expression in screen and rescore
__device__ __forceinline__ float t_row(float zn1) {
    return fmaf(zn1, C1_T, C0_T);
}

// ---------------- kernel 1: codebook -> bf16 + enorm (fused) -----------------
__global__ void k_cbprep(const float* __restrict__ cb) {
    const int warp = (blockIdx.x * 256 + threadIdx.x) >> 5;
    const int lane = threadIdx.x & 31;
    const float* src = cb + (size_t)warp * D_DIM;
    float s = 0.f;
#pragma unroll
    for (int i = 0; i < 8; i++) {
        float v = src[lane + i * 32];
        s = fmaf(v, v, s);
    }
#pragma unroll
    for (int o = 16; o; o >>= 1) s += __shfl_xor_sync(0xffffffffu, s, o);
    if (lane == 0) g_enorm[warp] = s;

    float4 v0 = *(const float4*)(src + lane * 8);
    float4 v1 = *(const float4*)(src + lane * 8 + 4);
    __nv_bfloat162 p0{__float2bfloat16_rn(v0.x), __float2bfloat16_rn(v0.y)};
    __nv_bfloat162 p1{__float2bfloat16_rn(v0.z), __float2bfloat16_rn(v0.w)};
    __nv_bfloat162 p2{__float2bfloat16_rn(v1.x), __float2bfloat16_rn(v1.y)};
    __nv_bfloat162 p3{__float2bfloat16_rn(v1.z), __float2bfloat16_rn(v1.w)};
    uint4 o;
    o.x = *(uint32_t*)&p0; o.y = *(uint32_t*)&p1;
    o.z = *(uint32_t*)&p2; o.w = *(uint32_t*)&p3;
    *(uint4*)(g_cbbf + (size_t)warp * D_DIM + lane * 8) = o;
}

// ---- kernel 2: fused z-prep + HMMA screen (round-8 mainloop, untouched) -----
#define SM_A    0
#define SM_B0   65536
#define SM_B1   131072
#define SMEM_TOTAL 196608
#define VPAD 257

__device__ __forceinline__ void stage_async(const __nv_bfloat16* __restrict__ g,
                                            uint32_t sdst, int tid) {
#pragma unroll
    for (int it = 0; it < 8; it++) {
        const int idx = it * 512 + tid;
        const int row = idx >> 5, ch = idx & 31;
        CP_ASYNC16(sdst + row * 512 + ((ch ^ (row & 7)) << 4),
                   g + (size_t)row * 256 + ch * 8);
    }
}

__global__ __launch_bounds__(512, 1) void k_screen(const float* __restrict__ z) {
    extern __shared__ char smem[];
    const int tid = threadIdx.x, w = tid >> 5, lane = tid & 31;
    const int wm = (w >> 2) * 32, wc = w & 3, wn = wc * 32;
    const int gid = lane >> 2, tg = lane & 3, ls = lane & 7;
    const int row0 = blockIdx.x * 128;
    const uint32_t sb = smem_u32(smem);

    // ---------- prologue: transpose z slice + norms + bf16 A tile ----------
    {
        const int b = row0 >> 10, hw0 = row0 & 1023;
        float* V = (float*)(smem + SM_B0);            // [32][VPAD] fp32
#pragma unroll 1
        for (int ch = 0; ch < 4; ch++) {
#pragma unroll
            for (int it = 0; it < 4; it++) {
                const int idx = it * 512 + tid;       // 0..2047
                const int c = idx >> 3, j = idx & 7;
                const float4 v4 = *(const float4*)(
                    z + (((size_t)b * 256 + c) << 10) + hw0 + ch * 32 + j * 4);
                const int hl = j * 4;
                V[(hl + 0) * VPAD + c] = v4.x;
                V[(hl + 1) * VPAD + c] = v4.y;
                V[(hl + 2) * VPAD + c] = v4.z;
                V[(hl + 3) * VPAD + c] = v4.w;
            }
            __syncthreads();
#pragma unroll
            for (int rr = 0; rr < 2; rr++) {
                const int r = w * 2 + rr;             // 0..31
                const int n = row0 + ch * 32 + r;
                float s = 0.f, s1 = 0.f;
#pragma unroll
                for (int i = 0; i < 8; i++) {         // EXACT validated norm order
                    const float v = V[r * VPAD + lane + i * 32];
                    s  = fmaf(v, v, s);
                    s1 += fabsf(v);
                }
#pragma unroll
                for (int o = 16; o; o >>= 1) {
                    s  += __shfl_xor_sync(0xffffffffu, s, o);
                    s1 += __shfl_xor_sync(0xffffffffu, s1, o);
                }
                if (lane == 0) { g_znorm[n] = s; g_zn1[n] = s1; }
                // pack bf16 A row (same swizzle stage_async produces)
                uint32_t pk[4];
#pragma unroll
                for (int q = 0; q < 4; q++) {
                    const float a0 = V[r * VPAD + lane * 8 + q * 2];
                    const float a1 = V[r * VPAD + lane * 8 + q * 2 + 1];
                    __nv_bfloat162 p{__float2bfloat16_rn(a0), __float2bfloat16_rn(a1)};
                    pk[q] = *(uint32_t*)&p;
                }
                const int row = ch * 32 + r;
                *(uint4*)(smem + SM_A + row * 512 + ((lane ^ (row & 7)) << 4)) =
                    make_uint4(pk[0], pk[1], pk[2], pk[3]);
            }
            __syncthreads();
        }
    }

    // ---------- stage first B tile, load row constants ----------
    stage_async(g_cbbf, sb + SM_B0, tid);
    CP_COMMIT();

    int rows[4]; float znr[4], Trw[4];
#pragma unroll
    for (int k = 0; k < 4; k++) {
        const int r = wm + (k >> 1) * 16 + (k & 1) * 8 + gid;
        rows[k] = r;
        znr[k]  = g_znorm[row0 + r];
        Trw[k]  = t_row(g_zn1[row0 + r]);
    }

    const int kmA = lane >> 4;
    const int kmB = (lane >> 3) & 1;
    uint32_t baA[2];
#pragma unroll
    for (int i = 0; i < 2; i++) {
        const int r = wm + i * 16 + ((lane >> 3) & 1) * 8 + ls;
        baA[i] = sb + SM_A + r * 512;
    }
    uint32_t boff[2];
#pragma unroll
    for (int p = 0; p < 2; p++) {
        const int r = wn + (p * 2 + (lane >> 4)) * 8 + ls;
        boff[p] = r * 512;
    }

    float acc[2][4][4];
#pragma unroll
    for (int i = 0; i < 2; i++)
#pragma unroll
        for (int j = 0; j < 4; j++)
#pragma unroll
            for (int c = 0; c < 4; c++) acc[i][j][c] = 0.f;

    CP_WAIT0();
    __syncthreads();

    for (int t = 0; t < NT; t++) {
        const uint32_t bbase = sb + ((t & 1) ? SM_B1 : SM_B0);
        if (t + 1 < NT) {
            stage_async(g_cbbf + (size_t)(t + 1) * 128 * D_DIM,
                        sb + (((t + 1) & 1) ? SM_B1 : SM_B0), tid);
            CP_COMMIT();
        }
#pragma unroll 4
        for (int kc = 0; kc < 16; kc++) {
            uint32_t a[2][4], bq[2][4];
            const uint32_t offA = (uint32_t)(((2 * kc + kmA) ^ ls) << 4);
            const uint32_t offB = (uint32_t)(((2 * kc + kmB) ^ ls) << 4);
            LDM4(a[0], baA[0] + offA);
            LDM4(a[1], baA[1] + offA);
            LDM4(bq[0], bbase + boff[0] + offB);
            LDM4(bq[1], bbase + boff[1] + offB);
#pragma unroll
            for (int i = 0; i < 2; i++)
#pragma unroll
                for (int j = 0; j < 4; j++)
                    MMA16816(acc[i][j], a[i], bq[j >> 1][(j & 1) * 2],
                             bq[j >> 1][(j & 1) * 2 + 1]);
        }

        // ---- all-register epilogue: per-warp min + superset mask (no enorm) ----
        float rmin[4] = {CUDART_INF_F, CUDART_INF_F, CUDART_INF_F, CUDART_INF_F};
#pragma unroll
        for (int i = 0; i < 2; i++)
#pragma unroll
            for (int j = 0; j < 4; j++)
#pragma unroll
                for (int c = 0; c < 4; c++) {
                    const int k = i * 2 + (c >> 1);
                    const float s = fmaf(-2.f, acc[i][j][c], znr[k]);
                    rmin[k] = fminf(rmin[k], s);
                }
#pragma unroll
        for (int k = 0; k < 4; k++) {
            rmin[k] = fminf(rmin[k], __shfl_xor_sync(0xffffffffu, rmin[k], 1));
            rmin[k] = fminf(rmin[k], __shfl_xor_sync(0xffffffffu, rmin[k], 2));
        }
        uint32_t m[4] = {0, 0, 0, 0};
#pragma unroll
        for (int i = 0; i < 2; i++)
#pragma unroll
            for (int j = 0; j < 4; j++)
#pragma unroll
                for (int c = 0; c < 4; c++) {
                    const int k = i * 2 + (c >> 1);
                    const float s = fmaf(-2.f, acc[i][j][c], znr[k]);
                    if (s < rmin[k] + Trw[k]) m[k] |= 1u << (j * 8 + tg * 2 + (c & 1));
                }
#pragma unroll
        for (int k = 0; k < 4; k++) {
            m[k] |= __shfl_xor_sync(0xffffffffu, m[k], 1);
            m[k] |= __shfl_xor_sync(0xffffffffu, m[k], 2);
        }
        if (tg == 0) {
#pragma unroll
            for (int k = 0; k < 4; k++) {
                g_mask[((size_t)(row0 + rows[k]) * NT + t) * 4 + wc] = m[k];
                g_tmin[(size_t)(row0 + rows[k]) * 256 + t * 4 + wc]  = rmin[k];
            }
        }
#pragma unroll
        for (int i = 0; i < 2; i++)
#pragma unroll
            for (int j = 0; j < 4; j++)
#pragma unroll
                for (int c = 0; c < 4; c++) acc[i][j][c] = 0.f;
        CP_WAIT0();
        __syncthreads();
    }
}

// ---------------- kernel 3: exact fp32 rescore (pipelined candidate dot) -----
__global__ void k_rescore(const float* __restrict__ z, const float* __restrict__ cb,
                          float* __restrict__ oidx) {
    __shared__ float zrow[256];
    __shared__ float smin2[64];
    __shared__ float sd[64];
    __shared__ int   si[64];
    const int row = blockIdx.x, tid = threadIdx.x;
    const int rb = row >> 10, rhw = row & 1023;
    const float4 tm4 = ((const float4*)g_tmin)[row * 64 + tid];
    const float tml = fminf(fminf(tm4.x, tm4.y), fminf(tm4.z, tm4.w));
    smin2[tid] = tml;
#pragma unroll
    for (int i = tid; i < 256; i += 64)
        zrow[i] = z[(((size_t)rb * 256 + i) << 10) + rhw];
    __syncthreads();
    for (int o = 32; o; o >>= 1) {
        if (tid < o) smin2[tid] = fminf(smin2[tid], smin2[tid + o]);
        __syncthreads();
    }
    const float m    = smin2[0];
    const float Trow = t_row(g_zn1[row]);
    const float zn   = g_znorm[row];
    const float tmv[4] = {tm4.x, tm4.y, tm4.z, tm4.w};

    float bd = CUDART_INF_F; int bi = 0x7fffffff;
#pragma unroll
    for (int q = 0; q < 4; q++) {
        if (tmv[q] < m + Trow) {
            uint32_t bits = g_mask[((size_t)row * NT + tid) * 4 + q];
            while (bits) {
                const int j = __ffs(bits) - 1; bits &= bits - 1;
                const int k = tid * 128 + q * 32 + j;
                const float4* e4 = (const float4*)(cb + (size_t)k * D_DIM);
                // double-buffered float4 chunk loads; fmaf order d0=0..255 UNCHANGED
                float4 buf0[8], buf1[8];
#pragma unroll
                for (int i = 0; i < 8; i++) buf0[i] = __ldg(e4 + i);
                float acc = 0.f;
#pragma unroll
                for (int ch = 0; ch < 8; ch++) {
                    const float4* cur = (ch & 1) ? buf1 : buf0;
                    float4*       nxt = (ch & 1) ? buf0 : buf1;
                    if (ch < 7) {
#pragma unroll
                        for (int i = 0; i < 8; i++) nxt[i] = __ldg(e4 + (ch + 1) * 8 + i);
                    }
#pragma unroll
                    for (int i = 0; i < 8; i++) {
                        const int d0 = ch * 32 + i * 4;
                        acc = fmaf(zrow[d0],     cur[i].x, acc);
                        acc = fmaf(zrow[d0 + 1], cur[i].y, acc);
                        acc = fmaf(zrow[d0 + 2], cur[i].z, acc);
                        acc = fmaf(zrow[d0 + 3], cur[i].w, acc);
                    }
                }
                const float s   = zn + __ldg(&g_enorm[k]);
                const float dsc = s - 2.0f * acc;
                if (dsc < bd || (dsc == bd && k < bi)) { bd = dsc; bi = k; }
            }
        }
    }
    sd[tid] = bd; si[tid] = bi;
    __syncthreads();
    for (int o = 32; o; o >>= 1) {
        if (tid < o) {
            const float d2 = sd[tid + o]; const int i2 = si[tid + o];
            if (d2 < sd[tid] || (d2 == sd[tid] && i2 < si[tid])) { sd[tid] = d2; si[tid] = i2; }
        }
        __syncthreads();
    }
    if (tid == 0) { g_idx[row] = si[0]; oidx[row] = (float)si[0]; }
}

// ---------------- kernel 4: gather + straight-through + loss partials --------
__global__ void k_gather(const float* __restrict__ z, const float* __restrict__ cb,
                         float* __restrict__ out) {
    const int c = blockIdx.x, b = blockIdx.y;
    const float* zp = z   + ((size_t)b * D_DIM + c) * HW;
    float*       op = out + ((size_t)b * D_DIM + c) * HW;
    float part = 0.f;
#pragma unroll
    for (int it = 0; it < 4; it++) {
        const int hw  = it * 256 + threadIdx.x;
        const int idx = g_idx[b * HW + hw];
        float q  = __ldg(cb + (size_t)idx * D_DIM + c);
        float zv = zp[hw];
        float t  = q - zv;
        op[hw]   = zv + t;
        part     = fmaf(t, t, part);
    }
    __shared__ float sm[8];
    const int lane = threadIdx.x & 31, ww = threadIdx.x >> 5;
#pragma unroll
    for (int o = 16; o; o >>= 1) part += __shfl_xor_sync(0xffffffffu, part, o);
    if (lane == 0) sm[ww] = part;
    __syncthreads();
    if (threadIdx.x == 0) {
        float s = 0.f;
        for (int i = 0; i < 8; i++) s += sm[i];
        g_partial[b * 256 + c] = s;
    }
}

// ---------------- kernel 5: loss finalize ------------------------------------
__global__ void k_loss(float* __restrict__ out) {
    __shared__ float sm[256];
    const int tid = threadIdx.x;
    float s = 0.f;
#pragma unroll
    for (int i = 0; i < 16; i++) s += g_partial[tid * 16 + i];
    sm[tid] = s;
    __syncthreads();
    for (int o = 128; o; o >>= 1) {
        if (tid < o) sm[tid] += sm[tid + o];
        __syncthreads();
    }
    if (tid == 0) {
        const float m = sm[0] / (float)ZQ_ELEMS;
        out[ZQ_ELEMS] = m + 0.25f * m;
    }
}

// ---------------- launcher ---------------------------------------------------
extern "C" void kernel_launch(void* const* d_in, const int* in_sizes, int n_in,
                              void* d_out, int out_size) {
    const float* z  = (const float*)d_in[0];
    const float* cb = (const float*)d_in[1];
    float* out = (float*)d_out;

    static int attr_set = 0;
    if (!attr_set) {
        cudaFuncSetAttribute(k_screen, cudaFuncAttributeMaxDynamicSharedMemorySize,
                             SMEM_TOTAL);
        attr_set = 1;
    }

    k_cbprep<<<1024, 256>>>(cb);
    k_screen<<<128, 512, SMEM_TOTAL>>>(z);
    k_rescore<<<N_ROWS, 64>>>(z, cb, out + ZQ_ELEMS + 1);
    dim3 gG(256, 16);
    k_gather<<<gG, 256>>>(z, cb, out);
    k_loss<<<1, 256>>>(out);
}

// round 11
// speedup vs baseline: 1.0252x; 1.0005x over previous
#include <cuda_runtime.h>
#include <cuda_bf16.h>
#include <math_constants.h>
#include <cstdint>

#define N_ROWS  16384       // b*h*w
#define D_DIM   256
#define K_CODES 8192
#define HW      1024
#define ZQ_ELEMS (16 * 256 * 1024)
#define NT      64          // code tiles of 128
#define C1_T    1.25e-6f    // per-row error slope (covers bf16 rounding of z,e)
#define C0_T    1.6e-4f     // fixed slack: fp32 reorder + expr rounding + grid ulps + enorm

// ---------------- scratch ----------------------------------------------------
__device__ __align__(16) __nv_bfloat16  g_cbbf[K_CODES * D_DIM];
__device__ float g_znorm[N_ROWS];
__device__ float g_zn1[N_ROWS];
__device__ float g_enorm[K_CODES];
__device__ float g_tmin[N_ROWS * 256];       // per (row, tile, code-quadrant) min
__device__ __align__(16) uint32_t g_mask[N_ROWS * NT * 4];
__device__ int   g_idx[N_ROWS];
__device__ float g_partial[4096];

__device__ __forceinline__ uint32_t smem_u32(const void* p) {
    uint32_t a;
    asm("{ .reg .u64 t; cvta.to.shared.u64 t, %1; cvt.u32.u64 %0, t; }" : "=r"(a) : "l"(p));
    return a;
}
#define LDM4(r, a) \
    asm volatile("ldmatrix.sync.aligned.m8n8.x4.shared.b16 {%0,%1,%2,%3}, [%4];" \
        : "=r"((r)[0]), "=r"((r)[1]), "=r"((r)[2]), "=r"((r)[3]) : "r"(a))
#define MMA16816(d, a, b0, b1) \
    asm volatile("mma.sync.aligned.m16n8k16.row.col.f32.bf16.bf16.f32 " \
        "{%0,%1,%2,%3}, {%4,%5,%6,%7}, {%8,%9}, {%0,%1,%2,%3};" \
        : "+f"((d)[0]), "+f"((d)[1]), "+f"((d)[2]), "+f"((d)[3]) \
        : "r"((a)[0]), "r"((a)[1]), "r"((a)[2]), "r"((a)[3]), "r"(b0), "r"(b1))
#define CP_ASYNC16(s, g) \
    asm volatile("cp.async.cg.shared.global [%0], [%1], 16;" :: "r"(s), "l"(g) : "memory")
#define CP_ASYNC4(s, g) \
    asm volatile("cp.async.ca.shared.global [%0], [%1], 4;" :: "r"(s), "l"(g) : "memory")
#define CP_COMMIT()  asm volatile("cp.async.commit_group;" ::: "memory")
#define CP_WAIT0()   asm volatile("cp.async.wait_group 0;" ::: "memory")

// threshold: identical expression in screen and rescore
__device__ __forceinline__ float t_row(float zn1) {
    return fmaf(zn1, C1_T, C0_T);
}

// ---------------- kernel 1: codebook -> bf16 + enorm (fused) -----------------
__global__ void k_cbprep(const float* __restrict__ cb) {
    const int warp = (blockIdx.x * 256 + threadIdx.x) >> 5;
    const int lane = threadIdx.x & 31;
    const float* src = cb + (size_t)warp * D_DIM;
    float s = 0.f;
#pragma unroll
    for (int i = 0; i < 8; i++) {
        float v = src[lane + i * 32];
        s = fmaf(v, v, s);
    }
#pragma unroll
    for (int o = 16; o; o >>= 1) s += __shfl_xor_sync(0xffffffffu, s, o);
    if (lane == 0) g_enorm[warp] = s;

    float4 v0 = *(const float4*)(src + lane * 8);
    float4 v1 = *(const float4*)(src + lane * 8 + 4);
    __nv_bfloat162 p0{__float2bfloat16_rn(v0.x), __float2bfloat16_rn(v0.y)};
    __nv_bfloat162 p1{__float2bfloat16_rn(v0.z), __float2bfloat16_rn(v0.w)};
    __nv_bfloat162 p2{__float2bfloat16_rn(v1.x), __float2bfloat16_rn(v1.y)};
    __nv_bfloat162 p3{__float2bfloat16_rn(v1.z), __float2bfloat16_rn(v1.w)};
    uint4 o;
    o.x = *(uint32_t*)&p0; o.y = *(uint32_t*)&p1;
    o.z = *(uint32_t*)&p2; o.w = *(uint32_t*)&p3;
    *(uint4*)(g_cbbf + (size_t)warp * D_DIM + lane * 8) = o;
}

// ---- kernel 2: fused z-prep (cp.async) + HMMA screen (round-8 mainloop) -----
#define SM_A    0
#define SM_B0   65536
#define SM_B1   131072
#define SMEM_TOTAL 196608
#define VROW 33   // floats per c-row in prologue buffer (32 data + 1 pad)

__device__ __forceinline__ void stage_async(const __nv_bfloat16* __restrict__ g,
                                            uint32_t sdst, int tid) {
#pragma unroll
    for (int it = 0; it < 8; it++) {
        const int idx = it * 512 + tid;
        const int row = idx >> 5, ch = idx & 31;
        CP_ASYNC16(sdst + row * 512 + ((ch ^ (row & 7)) << 4),
                   g + (size_t)row * 256 + ch * 8);
    }
}

__global__ __launch_bounds__(512, 1) void k_screen(const float* __restrict__ z) {
    extern __shared__ char smem[];
    const int tid = threadIdx.x, w = tid >> 5, lane = tid & 31;
    const int wm = (w >> 2) * 32, wc = w & 3, wn = wc * 32;
    const int gid = lane >> 2, tg = lane & 3, ls = lane & 7;
    const int row0 = blockIdx.x * 128;
    const uint32_t sb = smem_u32(smem);

    // ---------- prestage B tile 0 into SM_B1 (overlaps entire prologue) -----
    stage_async(g_cbbf, sb + SM_B1, tid);
    CP_COMMIT();

    // ---------- prologue: cp.async z chunks + norms + bf16 A tile ------------
    {
        const int b = row0 >> 10, hw0 = row0 & 1023;
        float* V = (float*)(smem + SM_B0);       // [256][VROW] floats, c-major
#pragma unroll 1
        for (int ch = 0; ch < 4; ch++) {
#pragma unroll
            for (int it = 0; it < 16; it++) {
                const int idx = it * 512 + tid;  // 0..8191
                const int c = idx >> 5, f = idx & 31;
                CP_ASYNC4(sb + SM_B0 + (uint32_t)(c * (VROW * 4) + f * 4),
                          z + (((size_t)b * 256 + c) << 10) + hw0 + ch * 32 + f);
            }
            CP_COMMIT();
            CP_WAIT0();
            __syncthreads();
#pragma unroll
            for (int rr = 0; rr < 2; rr++) {
                const int r = w * 2 + rr;        // hw within chunk, 0..31
                const int n = row0 + ch * 32 + r;
                float s = 0.f, s1 = 0.f;
#pragma unroll
                for (int i = 0; i < 8; i++) {    // EXACT validated norm order
                    const float v = V[(lane + i * 32) * VROW + r];
                    s  = fmaf(v, v, s);
                    s1 += fabsf(v);
                }
#pragma unroll
                for (int o = 16; o; o >>= 1) {
                    s  += __shfl_xor_sync(0xffffffffu, s, o);
                    s1 += __shfl_xor_sync(0xffffffffu, s1, o);
                }
                if (lane == 0) { g_znorm[n] = s; g_zn1[n] = s1; }
                // pack bf16 pairs; bytes identical to the validated uint4 writes
                const int row = ch * 32 + r;
#pragma unroll
                for (int p = 0; p < 4; p++) {
                    const int u = lane + 32 * p;           // pair index 0..127
                    const float a0 = V[(2 * u) * VROW + r];
                    const float a1 = V[(2 * u + 1) * VROW + r];
                    __nv_bfloat162 pr{__float2bfloat16_rn(a0), __float2bfloat16_rn(a1)};
                    const uint32_t byte = (uint32_t)(row * 512
                        + ((((u >> 2) ^ (row & 7)) << 4) | ((u & 3) * 4)));
                    *(uint32_t*)(smem + SM_A + byte) = *(uint32_t*)&pr;
                }
            }
            __syncthreads();
        }
    }

    // ---------- row constants ----------
    int rows[4]; float znr[4], Trw[4];
#pragma unroll
    for (int k = 0; k < 4; k++) {
        const int r = wm + (k >> 1) * 16 + (k & 1) * 8 + gid;
        rows[k] = r;
        znr[k]  = g_znorm[row0 + r];
        Trw[k]  = t_row(g_zn1[row0 + r]);
    }

    const int kmA = lane >> 4;
    const int kmB = (lane >> 3) & 1;
    uint32_t baA[2];
#pragma unroll
    for (int i = 0; i < 2; i++) {
        const int r = wm + i * 16 + ((lane >> 3) & 1) * 8 + ls;
        baA[i] = sb + SM_A + r * 512;
    }
    uint32_t boff[2];
#pragma unroll
    for (int p = 0; p < 2; p++) {
        const int r = wn + (p * 2 + (lane >> 4)) * 8 + ls;
        boff[p] = r * 512;
    }

    float acc[2][4][4];
#pragma unroll
    for (int i = 0; i < 2; i++)
#pragma unroll
        for (int j = 0; j < 4; j++)
#pragma unroll
            for (int c = 0; c < 4; c++) acc[i][j][c] = 0.f;

    CP_WAIT0();
    __syncthreads();

    for (int t = 0; t < NT; t++) {
        const uint32_t bbase = sb + ((t & 1) ? SM_B0 : SM_B1);   // tile 0 in B1
        if (t + 1 < NT) {
            stage_async(g_cbbf + (size_t)(t + 1) * 128 * D_DIM,
                        sb + (((t + 1) & 1) ? SM_B0 : SM_B1), tid);
            CP_COMMIT();
        }
#pragma unroll 4
        for (int kc = 0; kc < 16; kc++) {
            uint32_t a[2][4], bq[2][4];
            const uint32_t offA = (uint32_t)(((2 * kc + kmA) ^ ls) << 4);
            const uint32_t offB = (uint32_t)(((2 * kc + kmB) ^ ls) << 4);
            LDM4(a[0], baA[0] + offA);
            LDM4(a[1], baA[1] + offA);
            LDM4(bq[0], bbase + boff[0] + offB);
            LDM4(bq[1], bbase + boff[1] + offB);
#pragma unroll
            for (int i = 0; i < 2; i++)
#pragma unroll
                for (int j = 0; j < 4; j++)
                    MMA16816(acc[i][j], a[i], bq[j >> 1][(j & 1) * 2],
                             bq[j >> 1][(j & 1) * 2 + 1]);
        }

        // ---- all-register epilogue: per-warp min + superset mask (no enorm) ----
        float rmin[4] = {CUDART_INF_F, CUDART_INF_F, CUDART_INF_F, CUDART_INF_F};
#pragma unroll
        for (int i = 0; i < 2; i++)
#pragma unroll
            for (int j = 0; j < 4; j++)
#pragma unroll
                for (int c = 0; c < 4; c++) {
                    const int k = i * 2 + (c >> 1);
                    const float s = fmaf(-2.f, acc[i][j][c], znr[k]);
                    rmin[k] = fminf(rmin[k], s);
                }
#pragma unroll
        for (int k = 0; k < 4; k++) {
            rmin[k] = fminf(rmin[k], __shfl_xor_sync(0xffffffffu, rmin[k], 1));
            rmin[k] = fminf(rmin[k], __shfl_xor_sync(0xffffffffu, rmin[k], 2));
        }
        uint32_t m[4] = {0, 0, 0, 0};
#pragma unroll
        for (int i = 0; i < 2; i++)
#pragma unroll
            for (int j = 0; j < 4; j++)
#pragma unroll
                for (int c = 0; c < 4; c++) {
                    const int k = i * 2 + (c >> 1);
                    const float s = fmaf(-2.f, acc[i][j][c], znr[k]);
                    if (s < rmin[k] + Trw[k]) m[k] |= 1u << (j * 8 + tg * 2 + (c & 1));
                }
#pragma unroll
        for (int k = 0; k < 4; k++) {
            m[k] |= __shfl_xor_sync(0xffffffffu, m[k], 1);
            m[k] |= __shfl_xor_sync(0xffffffffu, m[k], 2);
        }
        if (tg == 0) {
#pragma unroll
            for (int k = 0; k < 4; k++) {
                g_mask[((size_t)(row0 + rows[k]) * NT + t) * 4 + wc] = m[k];
                g_tmin[(size_t)(row0 + rows[k]) * 256 + t * 4 + wc]  = rmin[k];
            }
        }
#pragma unroll
        for (int i = 0; i < 2; i++)
#pragma unroll
            for (int j = 0; j < 4; j++)
#pragma unroll
                for (int c = 0; c < 4; c++) acc[i][j][c] = 0.f;
        CP_WAIT0();
        __syncthreads();
    }
}

// ---------------- kernel 3: exact fp32 rescore (pipelined candidate dot) -----
__global__ void k_rescore(const float* __restrict__ z, const float* __restrict__ cb,
                          float* __restrict__ oidx) {
    __shared__ float zrow[256];
    __shared__ float smin2[64];
    __shared__ float sd[64];
    __shared__ int   si[64];
    const int row = blockIdx.x, tid = threadIdx.x;
    const int rb = row >> 10, rhw = row & 1023;
    const float4 tm4 = ((const float4*)g_tmin)[row * 64 + tid];
    const float tml = fminf(fminf(tm4.x, tm4.y), fminf(tm4.z, tm4.w));
    smin2[tid] = tml;
#pragma unroll
    for (int i = tid; i < 256; i += 64)
        zrow[i] = z[(((size_t)rb * 256 + i) << 10) + rhw];
    __syncthreads();
    for (int o = 32; o; o >>= 1) {
        if (tid < o) smin2[tid] = fminf(smin2[tid], smin2[tid + o]);
        __syncthreads();
    }
    const float m    = smin2[0];
    const float Trow = t_row(g_zn1[row]);
    const float zn   = g_znorm[row];
    const float tmv[4] = {tm4.x, tm4.y, tm4.z, tm4.w};

    float bd = CUDART_INF_F; int bi = 0x7fffffff;
#pragma unroll
    for (int q = 0; q < 4; q++) {
        if (tmv[q] < m + Trow) {
            uint32_t bits = g_mask[((size_t)row * NT + tid) * 4 + q];
            while (bits) {
                const int j = __ffs(bits) - 1; bits &= bits - 1;
                const int k = tid * 128 + q * 32 + j;
                const float4* e4 = (const float4*)(cb + (size_t)k * D_DIM);
                // double-buffered float4 chunk loads; fmaf order d0=0..255 UNCHANGED
                float4 buf0[8], buf1[8];
#pragma unroll
                for (int i = 0; i < 8; i++) buf0[i] = __ldg(e4 + i);
                float acc = 0.f;
#pragma unroll
                for (int ch = 0; ch < 8; ch++) {
                    const float4* cur = (ch & 1) ? buf1 : buf0;
                    float4*       nxt = (ch & 1) ? buf0 : buf1;
                    if (ch < 7) {
#pragma unroll
                        for (int i = 0; i < 8; i++) nxt[i] = __ldg(e4 + (ch + 1) * 8 + i);
                    }
#pragma unroll
                    for (int i = 0; i < 8; i++) {
                        const int d0 = ch * 32 + i * 4;
                        acc = fmaf(zrow[d0],     cur[i].x, acc);
                        acc = fmaf(zrow[d0 + 1], cur[i].y, acc);
                        acc = fmaf(zrow[d0 + 2], cur[i].z, acc);
                        acc = fmaf(zrow[d0 + 3], cur[i].w, acc);
                    }
                }
                const float s   = zn + __ldg(&g_enorm[k]);
                const float dsc = s - 2.0f * acc;
                if (dsc < bd || (dsc == bd && k < bi)) { bd = dsc; bi = k; }
            }
        }
    }
    sd[tid] = bd; si[tid] = bi;
    __syncthreads();
    for (int o = 32; o; o >>= 1) {
        if (tid < o) {
            const float d2 = sd[tid + o]; const int i2 = si[tid + o];
            if (d2 < sd[tid] || (d2 == sd[tid] && i2 < si[tid])) { sd[tid] = d2; si[tid] = i2; }
        }
        __syncthreads();
    }
    if (tid == 0) { g_idx[row] = si[0]; oidx[row] = (float)si[0]; }
}

// ---------------- kernel 4: gather + straight-through + loss partials --------
__global__ void k_gather(const float* __restrict__ z, const float* __restrict__ cb,
                         float* __restrict__ out) {
    const int c = blockIdx.x, b = blockIdx.y;
    const float* zp = z   + ((size_t)b * D_DIM + c) * HW;
    float*       op = out + ((size_t)b * D_DIM + c) * HW;
    float part = 0.f;
#pragma unroll
    for (int it = 0; it < 4; it++) {
        const int hw  = it * 256 + threadIdx.x;
        const int idx = g_idx[b * HW + hw];
        float q  = __ldg(cb + (size_t)idx * D_DIM + c);
        float zv = zp[hw];
        float t  = q - zv;
        op[hw]   = zv + t;
        part     = fmaf(t, t, part);
    }
    __shared__ float sm[8];
    const int lane = threadIdx.x & 31, ww = threadIdx.x >> 5;
#pragma unroll
    for (int o = 16; o; o >>= 1) part += __shfl_xor_sync(0xffffffffu, part, o);
    if (lane == 0) sm[ww] = part;
    __syncthreads();
    if (threadIdx.x == 0) {
        float s = 0.f;
        for (int i = 0; i < 8; i++) s += sm[i];
        g_partial[b * 256 + c] = s;
    }
}

// ---------------- kernel 5: loss finalize ------------------------------------
__global__ void k_loss(float* __restrict__ out) {
    __shared__ float sm[256];
    const int tid = threadIdx.x;
    float s = 0.f;
#pragma unroll
    for (int i = 0; i < 16; i++) s += g_partial[tid * 16 + i];
    sm[tid] = s;
    __syncthreads();
    for (int o = 128; o; o >>= 1) {
        if (tid < o) sm[tid] += sm[tid + o];
        __syncthreads();
    }
    if (tid == 0) {
        const float m = sm[0] / (float)ZQ_ELEMS;
        out[ZQ_ELEMS] = m + 0.25f * m;
    }
}

// ---------------- launcher ---------------------------------------------------
extern "C" void kernel_launch(void* const* d_in, const int* in_sizes, int n_in,
                              void* d_out, int out_size) {
    const float* z  = (const float*)d_in[0];
    const float* cb = (const float*)d_in[1];
    float* out = (float*)d_out;

    static int attr_set = 0;
    if (!attr_set) {
        cudaFuncSetAttribute(k_screen, cudaFuncAttributeMaxDynamicSharedMemorySize,
                             SMEM_TOTAL);
        attr_set = 1;
    }

    k_cbprep<<<1024, 256>>>(cb);
    k_screen<<<128, 512, SMEM_TOTAL>>>(z);
    k_rescore<<<N_ROWS, 64>>>(z, cb, out + ZQ_ELEMS + 1);
    dim3 gG(256, 16);
    k_gather<<<gG, 256>>>(z, cb, out);
    k_loss<<<1, 256>>>(out);
}

// round 12
// speedup vs baseline: 1.0403x; 1.0147x over previous
#include <cuda_runtime.h>
#include <cuda_bf16.h>
#include <math_constants.h>
#include <cstdint>

#define N_ROWS  16384       // b*h*w
#define D_DIM   256
#define K_CODES 8192
#define HW      1024
#define ZQ_ELEMS (16 * 256 * 1024)
#define NT      64          // code tiles of 128
#define C1_T    1.25e-6f    // per-row error slope (covers bf16 rounding of z,e)
#define C0_T    1.6e-4f     // fixed slack: fp32 reorder + expr rounding + grid ulps + enorm

// ---------------- scratch ----------------------------------------------------
__device__ __align__(16) float          g_zt[N_ROWS * D_DIM];
__device__ __align__(16) __nv_bfloat16  g_zbf[N_ROWS * D_DIM];
__device__ __align__(16) __nv_bfloat16  g_cbbf[K_CODES * D_DIM];
__device__ float g_znorm[N_ROWS];
__device__ float g_zn1[N_ROWS];
__device__ float g_enorm[K_CODES];
__device__ float g_tmin[N_ROWS * 256];       // per (row, tile, code-quadrant) min
__device__ __align__(16) uint32_t g_mask[N_ROWS * NT * 4];
__device__ int   g_idx[N_ROWS];
__device__ float g_partial[4096];

__device__ __forceinline__ uint32_t smem_u32(const void* p) {
    uint32_t a;
    asm("{ .reg .u64 t; cvta.to.shared.u64 t, %1; cvt.u32.u64 %0, t; }" : "=r"(a) : "l"(p));
    return a;
}
#define LDM4(r, a) \
    asm volatile("ldmatrix.sync.aligned.m8n8.x4.shared.b16 {%0,%1,%2,%3}, [%4];" \
        : "=r"((r)[0]), "=r"((r)[1]), "=r"((r)[2]), "=r"((r)[3]) : "r"(a))
#define MMA16816(d, a, b0, b1) \
    asm volatile("mma.sync.aligned.m16n8k16.row.col.f32.bf16.bf16.f32 " \
        "{%0,%1,%2,%3}, {%4,%5,%6,%7}, {%8,%9}, {%0,%1,%2,%3};" \
        : "+f"((d)[0]), "+f"((d)[1]), "+f"((d)[2]), "+f"((d)[3]) \
        : "r"((a)[0]), "r"((a)[1]), "r"((a)[2]), "r"((a)[3]), "r"(b0), "r"(b1))
#define CP_ASYNC16(s, g) \
    asm volatile("cp.async.cg.shared.global [%0], [%1], 16;" :: "r"(s), "l"(g) : "memory")
#define CP_COMMIT()  asm volatile("cp.async.commit_group;" ::: "memory")
#define CP_WAIT0()   asm volatile("cp.async.wait_group 0;" ::: "memory")

// threshold: identical expression in screen and rescore
__device__ __forceinline__ float t_row(float zn1) {
    return fmaf(zn1, C1_T, C0_T);
}

// ---- kernel 1: fused transpose + bf16 copy + znorm/zn1 (R7-validated) -------
__global__ void k_tz(const float* __restrict__ z) {
    __shared__ float t[256][33];
    const int b = blockIdx.y, hw0 = blockIdx.x * 32;
    const int tid = threadIdx.x, w = tid >> 5, lane = tid & 31;
#pragma unroll 8
    for (int it = 0; it < 32; it++) {
        const int idx = it * 256 + tid;
        const int c = idx >> 5, hw = idx & 31;
        t[c][hw] = z[(((size_t)b * 256 + c) << 10) + hw0 + hw];
    }
    __syncthreads();
#pragma unroll
    for (int rr = 0; rr < 4; rr++) {
        const int r = w * 4 + rr;
        const int n = b * HW + hw0 + r;
        float s = 0.f, s1 = 0.f;
#pragma unroll
        for (int i = 0; i < 8; i++) {
            const float v = t[lane + i * 32][r];     // same serial order as k_norms
            s  = fmaf(v, v, s);
            s1 += fabsf(v);
        }
#pragma unroll
        for (int o = 16; o; o >>= 1) {
            s  += __shfl_xor_sync(0xffffffffu, s, o);
            s1 += __shfl_xor_sync(0xffffffffu, s1, o);
        }
        if (lane == 0) { g_znorm[n] = s; g_zn1[n] = s1; }
#pragma unroll
        for (int i = 0; i < 8; i++) {
            const int c = lane + i * 32;
            const float v = t[c][r];
            g_zt[(size_t)n * D_DIM + c]  = v;
            g_zbf[(size_t)n * D_DIM + c] = __float2bfloat16_rn(v);
        }
    }
}

// ---------------- kernel 2: codebook -> bf16 + enorm (fused) -----------------
__global__ void k_cbprep(const float* __restrict__ cb) {
    const int warp = (blockIdx.x * 256 + threadIdx.x) >> 5;
    const int lane = threadIdx.x & 31;
    const float* src = cb + (size_t)warp * D_DIM;
    float s = 0.f;
#pragma unroll
    for (int i = 0; i < 8; i++) {
        float v = src[lane + i * 32];
        s = fmaf(v, v, s);
    }
#pragma unroll
    for (int o = 16; o; o >>= 1) s += __shfl_xor_sync(0xffffffffu, s, o);
    if (lane == 0) g_enorm[warp] = s;

    float4 v0 = *(const float4*)(src + lane * 8);
    float4 v1 = *(const float4*)(src + lane * 8 + 4);
    __nv_bfloat162 p0{__float2bfloat16_rn(v0.x), __float2bfloat16_rn(v0.y)};
    __nv_bfloat162 p1{__float2bfloat16_rn(v0.z), __float2bfloat16_rn(v0.w)};
    __nv_bfloat162 p2{__float2bfloat16_rn(v1.x), __float2bfloat16_rn(v1.y)};
    __nv_bfloat162 p3{__float2bfloat16_rn(v1.z), __float2bfloat16_rn(v1.w)};
    uint4 o;
    o.x = *(uint32_t*)&p0; o.y = *(uint32_t*)&p1;
    o.z = *(uint32_t*)&p2; o.w = *(uint32_t*)&p3;
    *(uint4*)(g_cbbf + (size_t)warp * D_DIM + lane * 8) = o;
}

// ---------------- kernel 3: HMMA bf16 screen GEMM + per-warp min/mask --------
#define SM_A    0
#define SM_B0   65536
#define SM_B1   131072
#define SMEM_TOTAL 196608

__device__ __forceinline__ void stage_async(const __nv_bfloat16* __restrict__ g,
                                            uint32_t sdst, int tid) {
#pragma unroll
    for (int it = 0; it < 8; it++) {
        const int idx = it * 512 + tid;
        const int row = idx >> 5, ch = idx & 31;
        CP_ASYNC16(sdst + row * 512 + ((ch ^ (row & 7)) << 4),
                   g + (size_t)row * 256 + ch * 8);
    }
}

__global__ __launch_bounds__(512, 1) void k_screen() {
    extern __shared__ char smem[];
    const int tid = threadIdx.x, w = tid >> 5, lane = tid & 31;
    const int wm = (w >> 2) * 32, wc = w & 3, wn = wc * 32;
    const int gid = lane >> 2, tg = lane & 3, ls = lane & 7;
    const int row0 = blockIdx.x * 128;
    const uint32_t sb = smem_u32(smem);

    stage_async(g_zbf + (size_t)row0 * D_DIM, sb + SM_A, tid);
    stage_async(g_cbbf, sb + SM_B0, tid);
    CP_COMMIT();

    int rows[4]; float znr[4], Trw[4];
#pragma unroll
    for (int k = 0; k < 4; k++) {
        const int r = wm + (k >> 1) * 16 + (k & 1) * 8 + gid;
        rows[k] = r;
        znr[k]  = g_znorm[row0 + r];
        Trw[k]  = t_row(g_zn1[row0 + r]);
    }

    const int kmA = lane >> 4;
    const int kmB = (lane >> 3) & 1;
    uint32_t baA[2];
#pragma unroll
    for (int i = 0; i < 2; i++) {
        const int r = wm + i * 16 + ((lane >> 3) & 1) * 8 + ls;
        baA[i] = sb + SM_A + r * 512;
    }
    uint32_t boff[2];
#pragma unroll
    for (int p = 0; p < 2; p++) {
        const int r = wn + (p * 2 + (lane >> 4)) * 8 + ls;
        boff[p] = r * 512;
    }

    float acc[2][4][4];
#pragma unroll
    for (int i = 0; i < 2; i++)
#pragma unroll
        for (int j = 0; j < 4; j++)
#pragma unroll
            for (int c = 0; c < 4; c++) acc[i][j][c] = 0.f;

    CP_WAIT0();
    __syncthreads();

    for (int t = 0; t < NT; t++) {
        const uint32_t bbase = sb + ((t & 1) ? SM_B1 : SM_B0);
        if (t + 1 < NT) {
            stage_async(g_cbbf + (size_t)(t + 1) * 128 * D_DIM,
                        sb + (((t + 1) & 1) ? SM_B1 : SM_B0), tid);
            CP_COMMIT();
        }
#pragma unroll 4
        for (int kc = 0; kc < 16; kc++) {
            uint32_t a[2][4], bq[2][4];
            const uint32_t offA = (uint32_t)(((2 * kc + kmA) ^ ls) << 4);
            const uint32_t offB = (uint32_t)(((2 * kc + kmB) ^ ls) << 4);
            LDM4(a[0], baA[0] + offA);
            LDM4(a[1], baA[1] + offA);
            LDM4(bq[0], bbase + boff[0] + offB);
            LDM4(bq[1], bbase + boff[1] + offB);
#pragma unroll
            for (int i = 0; i < 2; i++)
#pragma unroll
                for (int j = 0; j < 4; j++)
                    MMA16816(acc[i][j], a[i], bq[j >> 1][(j & 1) * 2],
                             bq[j >> 1][(j & 1) * 2 + 1]);
        }

        // ---- all-register epilogue: per-warp min + superset mask (no enorm) ----
        float rmin[4] = {CUDART_INF_F, CUDART_INF_F, CUDART_INF_F, CUDART_INF_F};
#pragma unroll
        for (int i = 0; i < 2; i++)
#pragma unroll
            for (int j = 0; j < 4; j++)
#pragma unroll
                for (int c = 0; c < 4; c++) {
                    const int k = i * 2 + (c >> 1);
                    const float s = fmaf(-2.f, acc[i][j][c], znr[k]);
                    rmin[k] = fminf(rmin[k], s);
                }
#pragma unroll
        for (int k = 0; k < 4; k++) {
            rmin[k] = fminf(rmin[k], __shfl_xor_sync(0xffffffffu, rmin[k], 1));
            rmin[k] = fminf(rmin[k], __shfl_xor_sync(0xffffffffu, rmin[k], 2));
        }
        uint32_t m[4] = {0, 0, 0, 0};
#pragma unroll
        for (int i = 0; i < 2; i++)
#pragma unroll
            for (int j = 0; j < 4; j++)
#pragma unroll
                for (int c = 0; c < 4; c++) {
                    const int k = i * 2 + (c >> 1);
                    const float s = fmaf(-2.f, acc[i][j][c], znr[k]);
                    if (s < rmin[k] + Trw[k]) m[k] |= 1u << (j * 8 + tg * 2 + (c & 1));
                }
#pragma unroll
        for (int k = 0; k < 4; k++) {
            m[k] |= __shfl_xor_sync(0xffffffffu, m[k], 1);
            m[k] |= __shfl_xor_sync(0xffffffffu, m[k], 2);
        }
        if (tg == 0) {
#pragma unroll
            for (int k = 0; k < 4; k++) {
                g_mask[((size_t)(row0 + rows[k]) * NT + t) * 4 + wc] = m[k];
                g_tmin[(size_t)(row0 + rows[k]) * 256 + t * 4 + wc]  = rmin[k];
            }
        }
#pragma unroll
        for (int i = 0; i < 2; i++)
#pragma unroll
            for (int j = 0; j < 4; j++)
#pragma unroll
                for (int c = 0; c < 4; c++) acc[i][j][c] = 0.f;
        CP_WAIT0();
        __syncthreads();
    }
}

// ---------------- kernel 4: exact fp32 rescore (pipelined candidate dot) -----
__global__ void k_rescore(const float* __restrict__ cb, float* __restrict__ oidx) {
    __shared__ float zrow[256];
    __shared__ float smin2[64];
    __shared__ float sd[64];
    __shared__ int   si[64];
    const int row = blockIdx.x, tid = threadIdx.x;
    const float4 tm4 = ((const float4*)g_tmin)[row * 64 + tid];
    const float tml = fminf(fminf(tm4.x, tm4.y), fminf(tm4.z, tm4.w));
    smin2[tid] = tml;
#pragma unroll
    for (int i = tid; i < 256; i += 64) zrow[i] = g_zt[(size_t)row * D_DIM + i];
    __syncthreads();
    for (int o = 32; o; o >>= 1) {
        if (tid < o) smin2[tid] = fminf(smin2[tid], smin2[tid + o]);
        __syncthreads();
    }
    const float m    = smin2[0];
    const float Trow = t_row(g_zn1[row]);
    const float zn   = g_znorm[row];
    const float tmv[4] = {tm4.x, tm4.y, tm4.z, tm4.w};

    float bd = CUDART_INF_F; int bi = 0x7fffffff;
#pragma unroll
    for (int q = 0; q < 4; q++) {
        if (tmv[q] < m + Trow) {
            uint32_t bits = g_mask[((size_t)row * NT + tid) * 4 + q];
            while (bits) {
                const int j = __ffs(bits) - 1; bits &= bits - 1;
                const int k = tid * 128 + q * 32 + j;
                const float4* e4 = (const float4*)(cb + (size_t)k * D_DIM);
                // double-buffered float4 chunk loads; fmaf order d0=0..255 UNCHANGED
                float4 buf0[8], buf1[8];
#pragma unroll
                for (int i = 0; i < 8; i++) buf0[i] = __ldg(e4 + i);
                float acc = 0.f;
#pragma unroll
                for (int ch = 0; ch < 8; ch++) {
                    const float4* cur = (ch & 1) ? buf1 : buf0;
                    float4*       nxt = (ch & 1) ? buf0 : buf1;
                    if (ch < 7) {
#pragma unroll
                        for (int i = 0; i < 8; i++) nxt[i] = __ldg(e4 + (ch + 1) * 8 + i);
                    }
#pragma unroll
                    for (int i = 0; i < 8; i++) {
                        const int d0 = ch * 32 + i * 4;
                        acc = fmaf(zrow[d0],     cur[i].x, acc);
                        acc = fmaf(zrow[d0 + 1], cur[i].y, acc);
                        acc = fmaf(zrow[d0 + 2], cur[i].z, acc);
                        acc = fmaf(zrow[d0 + 3], cur[i].w, acc);
                    }
                }
                const float s   = zn + __ldg(&g_enorm[k]);
                const float dsc = s - 2.0f * acc;
                if (dsc < bd || (dsc == bd && k < bi)) { bd = dsc; bi = k; }
            }
        }
    }
    sd[tid] = bd; si[tid] = bi;
    __syncthreads();
    for (int o = 32; o; o >>= 1) {
        if (tid < o) {
            const float d2 = sd[tid + o]; const int i2 = si[tid + o];
            if (d2 < sd[tid] || (d2 == sd[tid] && i2 < si[tid])) { sd[tid] = d2; si[tid] = i2; }
        }
        __syncthreads();
    }
    if (tid == 0) { g_idx[row] = si[0]; oidx[row] = (float)si[0]; }
}

// ---------------- kernel 5: gather + straight-through + loss partials --------
__global__ void k_gather(const float* __restrict__ z, const float* __restrict__ cb,
                         float* __restrict__ out) {
    const int c = blockIdx.x, b = blockIdx.y;
    const float* zp = z   + ((size_t)b * D_DIM + c) * HW;
    float*       op = out + ((size_t)b * D_DIM + c) * HW;
    float part = 0.f;
#pragma unroll
    for (int it = 0; it < 4; it++) {
        const int hw  = it * 256 + threadIdx.x;
        const int idx = g_idx[b * HW + hw];
        float q  = __ldg(cb + (size_t)idx * D_DIM + c);
        float zv = zp[hw];
        float t  = q - zv;
        op[hw]   = zv + t;
        part     = fmaf(t, t, part);
    }
    __shared__ float sm[8];
    const int lane = threadIdx.x & 31, ww = threadIdx.x >> 5;
#pragma unroll
    for (int o = 16; o; o >>= 1) part += __shfl_xor_sync(0xffffffffu, part, o);
    if (lane == 0) sm[ww] = part;
    __syncthreads();
    if (threadIdx.x == 0) {
        float s = 0.f;
        for (int i = 0; i < 8; i++) s += sm[i];
        g_partial[b * 256 + c] = s;
    }
}

// ---------------- kernel 6: loss finalize ------------------------------------
__global__ void k_loss(float* __restrict__ out) {
    __shared__ float sm[256];
    const int tid = threadIdx.x;
    float s = 0.f;
#pragma unroll
    for (int i = 0; i < 16; i++) s += g_partial[tid * 16 + i];
    sm[tid] = s;
    __syncthreads();
    for (int o = 128; o; o >>= 1) {
        if (tid < o) sm[tid] += sm[tid + o];
        __syncthreads();
    }
    if (tid == 0) {
        const float m = sm[0] / (float)ZQ_ELEMS;
        out[ZQ_ELEMS] = m + 0.25f * m;
    }
}

// ---------------- launcher ---------------------------------------------------
extern "C" void kernel_launch(void* const* d_in, const int* in_sizes, int n_in,
                              void* d_out, int out_size) {
    const float* z  = (const float*)d_in[0];
    const float* cb = (const float*)d_in[1];
    float* out = (float*)d_out;

    static int attr_set = 0;
    if (!attr_set) {
        cudaFuncSetAttribute(k_screen, cudaFuncAttributeMaxDynamicSharedMemorySize,
                             SMEM_TOTAL);
        attr_set = 1;
    }

    dim3 gT(32, 16);
    k_tz<<<gT, 256>>>(z);
    k_cbprep<<<1024, 256>>>(cb);
    k_screen<<<128, 512, SMEM_TOTAL>>>();
    k_rescore<<<N_ROWS, 64>>>(cb, out + ZQ_ELEMS + 1);
    dim3 gG(256, 16);
    k_gather<<<gG, 256>>>(z, cb, out);
    k_loss<<<1, 256>>>(out);
}